// round 1
// baseline (speedup 1.0000x reference)
#include <cuda_runtime.h>

// Problem constants (fixed shapes from reference setup_inputs)
#define ROWS   153600      // N*M*T
#define D      256
#define D4     64          // D/4
#define KCLS   5
#define NB     256         // N
#define MB     2           // M
#define TB     300         // T
#define TOPK   64
#define CC     3           // C
#define VV     25          // V
#define SEL_ELEMS (NB*CC*TOPK*VV*MB)   // 2,457,600
#define EPSF   1e-8f

// ---------------- scratch (device globals; no allocations) ----------------
__device__ float  g_sums[KCLS*D];
__device__ int    g_counts[KCLS];
__device__ float  g_cm[KCLS*D];
__device__ float  g_inter[KCLS];
__device__ double g_Sb;
__device__ double g_Sw;
__device__ float  g_fs[ROWS];
__device__ int    g_idx[NB*TOPK];

// ---------------- kernel 0: zero accumulators ----------------
__global__ void k_init() {
    int i = blockIdx.x * blockDim.x + threadIdx.x;
    if (i < KCLS*D) g_sums[i] = 0.f;
    if (i < KCLS)   g_counts[i] = 0;
    if (i == 0)     g_Sw = 0.0;
}

// ---------------- kernel 1: per-class sums + counts ----------------
// Warp-per-row, float4 loads. 8 private shared copies of [KCLS][D4] float4
// (one per warp) -> no races, no atomics in the hot loop.
__global__ void k_segsum(const float4* __restrict__ xT, const int* __restrict__ lab) {
    __shared__ float4 s_sums[8][KCLS][D4];   // 40 KB
    __shared__ int    s_cnt[KCLS];
    const int tid  = threadIdx.x;
    const int w    = tid >> 5;
    const int lane = tid & 31;

    for (int i = tid; i < 8*KCLS*D4; i += blockDim.x)
        ((float4*)s_sums)[i] = make_float4(0.f, 0.f, 0.f, 0.f);
    if (tid < KCLS) s_cnt[tid] = 0;
    __syncthreads();

    const int warpsTotal = gridDim.x * 8;
    for (int r = blockIdx.x * 8 + w; r < ROWS; r += warpsTotal) {
        const int l = lab[r];
        const float4 a = xT[(size_t)r * D4 + lane];
        const float4 b = xT[(size_t)r * D4 + 32 + lane];
        float4* p = &s_sums[w][l][lane];
        p->x += a.x; p->y += a.y; p->z += a.z; p->w += a.w;
        float4* q = &s_sums[w][l][lane + 32];
        q->x += b.x; q->y += b.y; q->z += b.z; q->w += b.w;
        if (lane == 0) atomicAdd(&s_cnt[l], 1);
    }
    __syncthreads();

    // flush: sum the 8 copies, then atomic into global
    for (int i = tid; i < KCLS*D4; i += blockDim.x) {
        const int k = i / D4, c = i % D4;
        float4 acc = make_float4(0.f, 0.f, 0.f, 0.f);
        #pragma unroll
        for (int cp = 0; cp < 8; cp++) {
            const float4 v = s_sums[cp][k][c];
            acc.x += v.x; acc.y += v.y; acc.z += v.z; acc.w += v.w;
        }
        float* gp = &g_sums[k*D + c*4];
        atomicAdd(gp+0, acc.x); atomicAdd(gp+1, acc.y);
        atomicAdd(gp+2, acc.z); atomicAdd(gp+3, acc.w);
    }
    if (tid < KCLS && s_cnt[tid] != 0) atomicAdd(&g_counts[tid], s_cnt[tid]);
}

// ---------------- kernel 2: class means, overall mean, inter, Sb ----------------
__global__ void k_stats() {
    const int tid = threadIdx.x;       // 256 threads, one block
    __shared__ float s_cnt[KCLS];
    __shared__ float red[8];
    __shared__ float s_inter[KCLS];
    if (tid < KCLS) s_cnt[tid] = (float)g_counts[tid];
    __syncthreads();

    float cm[KCLS];
    float total = 0.f;
    #pragma unroll
    for (int k = 0; k < KCLS; k++) {
        const float s = g_sums[k*D + tid];
        total += s;
        cm[k] = s / fmaxf(s_cnt[k], 1.f);
        g_cm[k*D + tid] = cm[k];
    }
    const float ov = total / (float)ROWS;

    #pragma unroll
    for (int k = 0; k < KCLS; k++) {
        const float d = cm[k] - ov;
        float v = d * d;
        #pragma unroll
        for (int off = 16; off; off >>= 1) v += __shfl_down_sync(0xffffffffu, v, off);
        if ((tid & 31) == 0) red[tid >> 5] = v;
        __syncthreads();
        if (tid == 0) {
            float s = 0.f;
            #pragma unroll
            for (int i = 0; i < 8; i++) s += red[i];
            s_inter[k] = s;
            g_inter[k] = s;
        }
        __syncthreads();
    }
    if (tid == 0) {
        double sb = 0.0;
        #pragma unroll
        for (int k = 0; k < KCLS; k++) sb += (double)s_cnt[k] * (double)s_inter[k];
        g_Sb = sb;
    }
}

// ---------------- kernel 3: per-row intra dist, Sw, frame scores ----------------
__global__ void k_intra(const float4* __restrict__ xT, const int* __restrict__ lab) {
    __shared__ float4 s_cm[KCLS][D4];   // 5 KB
    __shared__ float  s_inter[KCLS];
    const int tid  = threadIdx.x;
    const int w    = tid >> 5;
    const int lane = tid & 31;

    for (int i = tid; i < KCLS*D4; i += blockDim.x)
        ((float4*)s_cm)[i] = ((const float4*)g_cm)[i];
    if (tid < KCLS) s_inter[tid] = g_inter[tid];
    __syncthreads();

    const int warpsTotal = gridDim.x * 8;
    double sw = 0.0;
    for (int r = blockIdx.x * 8 + w; r < ROWS; r += warpsTotal) {
        const int l = lab[r];
        const float4 a  = xT[(size_t)r * D4 + lane];
        const float4 b  = xT[(size_t)r * D4 + 32 + lane];
        const float4 ma = s_cm[l][lane];
        const float4 mb = s_cm[l][lane + 32];
        float d, v = 0.f;
        d = a.x - ma.x; v += d*d;  d = a.y - ma.y; v += d*d;
        d = a.z - ma.z; v += d*d;  d = a.w - ma.w; v += d*d;
        d = b.x - mb.x; v += d*d;  d = b.y - mb.y; v += d*d;
        d = b.z - mb.z; v += d*d;  d = b.w - mb.w; v += d*d;
        #pragma unroll
        for (int off = 16; off; off >>= 1) v += __shfl_down_sync(0xffffffffu, v, off);
        if (lane == 0) {
            sw += (double)v;
            g_fs[r] = s_inter[l] / (v + EPSF);
        }
    }
    if (lane == 0 && sw != 0.0) atomicAdd(&g_Sw, sw);
}

// ---------------- kernel 4: top-64 frames per sample ----------------
// One block per n. Exact jax.lax.top_k semantics: rank by (value desc, index asc),
// select rank<TOPK, emit in ascending index order (== jnp.sort of top_k indices).
__global__ void k_topk() {
    __shared__ float s_v[TB];
    __shared__ unsigned char s_flag[TB];
    const int n = blockIdx.x;
    const int t = threadIdx.x;
    if (t < TB) {
        const float a = g_fs[(n*2 + 0)*TB + t];
        const float b = g_fs[(n*2 + 1)*TB + t];
        s_v[t] = 0.5f * (a + b);
    }
    __syncthreads();
    if (t < TB) {
        const float v = s_v[t];
        int rank = 0;
        for (int j = 0; j < TB; j++) {
            const float vj = s_v[j];
            rank += (vj > v) || (vj == v && j < t);
        }
        s_flag[t] = (rank < TOPK) ? 1 : 0;
    }
    __syncthreads();
    if (t < TB && s_flag[t]) {
        int pos = 0;
        for (int j = 0; j < t; j++) pos += s_flag[j];
        g_idx[n*TOPK + pos] = t;
    }
}

// ---------------- kernel 5: gather selected frames + write loss ----------------
// x: [N, C, T, V, M]; read as float2 (M=2 contiguous). Output base may be offset
// by 1 float (loss) -> misaligned for float2 stores, so store scalars.
__global__ void k_gather(const float2* __restrict__ x, float* __restrict__ out, int sel_off) {
    const long long TOT = (long long)NB * CC * TOPK * VV;  // float2 elements
    const long long i = (long long)blockIdx.x * blockDim.x + threadIdx.x;
    if (i == 0 && sel_off >= 1)
        out[0] = (float)(g_Sw / (g_Sb + 1e-8));
    if (i < TOT) {
        long long r = i;
        const int v = (int)(r % VV); r /= VV;
        const int j = (int)(r % TOPK); r /= TOPK;
        const int c = (int)(r % CC);
        const int n = (int)(r / CC);
        const int t = g_idx[n*TOPK + j];
        const long long src = (((long long)(n*CC + c)) * TB + t) * VV + v;
        const float2 val = x[src];
        float* op = out + sel_off + 2*i;
        op[0] = val.x;
        op[1] = val.y;
    }
}

extern "C" void kernel_launch(void* const* d_in, const int* in_sizes, int n_in,
                              void* d_out, int out_size) {
    const float4* xT  = (const float4*)d_in[1];   // x_T [153600, 256]
    const int*    lab = (const int*)d_in[2];      // labels [153600] int32
    const float2* x   = (const float2*)d_in[0];   // x [256,3,300,25,2]
    float* out = (float*)d_out;

    const int sel_off = out_size - SEL_ELEMS;     // loss scalar(s) precede x_select

    k_init<<<5, 256>>>();
    k_segsum<<<592, 256>>>(xT, lab);
    k_stats<<<1, 256>>>();
    k_intra<<<592, 256>>>(xT, lab);
    k_topk<<<NB, 320>>>();
    const long long tot2 = (long long)NB * CC * TOPK * VV;
    k_gather<<<(int)((tot2 + 255) / 256), 256>>>(x, out, sel_off);
}

// round 2
// speedup vs baseline: 1.3102x; 1.3102x over previous
#include <cuda_runtime.h>

// Problem constants (fixed shapes from reference setup_inputs)
#define ROWS   153600      // N*M*T
#define D      256
#define D4     64          // D/4
#define KCLS   5
#define NB     256         // N
#define MB     2           // M
#define TB     300         // T
#define TOPK   64
#define CC     3           // C
#define VV     25          // V
#define SEL_ELEMS (NB*CC*TOPK*VV*MB)   // 2,457,600
#define EPSF   1e-8f

// ---------------- scratch (device globals; no allocations) ----------------
__device__ float  g_sums[KCLS*D];
__device__ int    g_counts[KCLS];
__device__ double g_Sb;
__device__ double g_Sw;
__device__ float  g_fs[ROWS];

// ---------------- kernel 0: zero accumulators ----------------
__global__ void k_init() {
    int i = blockIdx.x * blockDim.x + threadIdx.x;
    if (i < KCLS*D) g_sums[i] = 0.f;
    if (i < KCLS)   g_counts[i] = 0;
    if (i == 0)     g_Sw = 0.0;
}

__device__ __forceinline__ void f4add(float4& d, const float4 a) {
    d.x += a.x; d.y += a.y; d.z += a.z; d.w += a.w;
}

// ---------------- kernel 1: per-class sums + counts ----------------
// Warp-per-4-rows, float4 loads (8 in flight). Per-lane REGISTER accumulators
// for the 5 classes (labels are warp-uniform -> uniform branch, no divergence,
// no smem RMW chain, no per-row atomics).
__global__ void __launch_bounds__(256) k_segsum(const float4* __restrict__ xT,
                                                const int* __restrict__ lab) {
    __shared__ float4 s_sums[8][KCLS][D4];   // 40 KB
    __shared__ int    s_cnt[KCLS];
    const int tid  = threadIdx.x;
    const int w    = tid >> 5;
    const int lane = tid & 31;
    if (tid < KCLS) s_cnt[tid] = 0;

    float4 c0a = {0,0,0,0}, c0b = {0,0,0,0};
    float4 c1a = {0,0,0,0}, c1b = {0,0,0,0};
    float4 c2a = {0,0,0,0}, c2b = {0,0,0,0};
    float4 c3a = {0,0,0,0}, c3b = {0,0,0,0};
    float4 c4a = {0,0,0,0}, c4b = {0,0,0,0};
    int cnt0 = 0, cnt1 = 0, cnt2 = 0, cnt3 = 0, cnt4 = 0;

#define ACCUM(l, a, b)                                        \
    if ((l) == 0)      { f4add(c0a, a); f4add(c0b, b); cnt0++; } \
    else if ((l) == 1) { f4add(c1a, a); f4add(c1b, b); cnt1++; } \
    else if ((l) == 2) { f4add(c2a, a); f4add(c2b, b); cnt2++; } \
    else if ((l) == 3) { f4add(c3a, a); f4add(c3b, b); cnt3++; } \
    else               { f4add(c4a, a); f4add(c4b, b); cnt4++; }

    const int gw = blockIdx.x * 8 + w;
    const int nw = gridDim.x * 8;
    for (int r0 = gw * 4; r0 < ROWS; r0 += nw * 4) {
        const int4 L = *(const int4*)(lab + r0);
        const size_t base = (size_t)r0 * D4;
        const float4 a0 = xT[base       + lane], b0 = xT[base +  32 + lane];
        const float4 a1 = xT[base +  64 + lane], b1 = xT[base +  96 + lane];
        const float4 a2 = xT[base + 128 + lane], b2 = xT[base + 160 + lane];
        const float4 a3 = xT[base + 192 + lane], b3 = xT[base + 224 + lane];
        ACCUM(L.x, a0, b0);
        ACCUM(L.y, a1, b1);
        ACCUM(L.z, a2, b2);
        ACCUM(L.w, a3, b3);
    }
#undef ACCUM

    // flush: per-warp regs -> smem, combine 8 copies, atomics to global
    s_sums[w][0][lane] = c0a;  s_sums[w][0][lane + 32] = c0b;
    s_sums[w][1][lane] = c1a;  s_sums[w][1][lane + 32] = c1b;
    s_sums[w][2][lane] = c2a;  s_sums[w][2][lane + 32] = c2b;
    s_sums[w][3][lane] = c3a;  s_sums[w][3][lane + 32] = c3b;
    s_sums[w][4][lane] = c4a;  s_sums[w][4][lane + 32] = c4b;
    __syncthreads();
    if (lane == 0) {
        atomicAdd(&s_cnt[0], cnt0); atomicAdd(&s_cnt[1], cnt1);
        atomicAdd(&s_cnt[2], cnt2); atomicAdd(&s_cnt[3], cnt3);
        atomicAdd(&s_cnt[4], cnt4);
    }
    __syncthreads();
    for (int i = tid; i < KCLS*D4; i += blockDim.x) {
        const int k = i / D4, c = i % D4;
        float4 acc = {0,0,0,0};
        #pragma unroll
        for (int cp = 0; cp < 8; cp++) f4add(acc, s_sums[cp][k][c]);
        float* gp = &g_sums[k*D + c*4];
        atomicAdd(gp+0, acc.x); atomicAdd(gp+1, acc.y);
        atomicAdd(gp+2, acc.z); atomicAdd(gp+3, acc.w);
    }
    if (tid < KCLS && s_cnt[tid] != 0) atomicAdd(&g_counts[tid], s_cnt[tid]);
}

// ---------------- kernel 2: [stats prologue] + per-row intra, Sw, scores ----
__device__ __forceinline__ float dist8(const float4 a, const float4 b,
                                       const float4 ma, const float4 mb) {
    float d, v = 0.f;
    d = a.x - ma.x; v += d*d;  d = a.y - ma.y; v += d*d;
    d = a.z - ma.z; v += d*d;  d = a.w - ma.w; v += d*d;
    d = b.x - mb.x; v += d*d;  d = b.y - mb.y; v += d*d;
    d = b.z - mb.z; v += d*d;  d = b.w - mb.w; v += d*d;
    return v;
}

__global__ void __launch_bounds__(256) k_intra(const float4* __restrict__ xT,
                                               const int* __restrict__ lab) {
    __shared__ float s_cm[KCLS*D];     // 5 KB (float4-aligned)
    __shared__ float s_inter[KCLS];
    __shared__ float s_cntf[KCLS];
    __shared__ float s_red[8];
    const int tid  = threadIdx.x;
    const int w    = tid >> 5;
    const int lane = tid & 31;

    // --- stats prologue (every block redundantly; g_sums is L2-resident) ---
    if (tid < KCLS) s_cntf[tid] = (float)g_counts[tid];
    __syncthreads();
    float cmv[KCLS];
    float tot = 0.f;
    #pragma unroll
    for (int k = 0; k < KCLS; k++) {
        const float s = g_sums[k*D + tid];
        tot += s;
        cmv[k] = s / fmaxf(s_cntf[k], 1.f);
        s_cm[k*D + tid] = cmv[k];
    }
    const float ov = tot / (float)ROWS;
    #pragma unroll
    for (int k = 0; k < KCLS; k++) {
        const float dd = cmv[k] - ov;
        float v = dd * dd;
        #pragma unroll
        for (int off = 16; off; off >>= 1) v += __shfl_down_sync(0xffffffffu, v, off);
        if (lane == 0) s_red[w] = v;
        __syncthreads();
        if (tid == 0) {
            float s = 0.f;
            #pragma unroll
            for (int i = 0; i < 8; i++) s += s_red[i];
            s_inter[k] = s;
        }
        __syncthreads();
    }
    if (blockIdx.x == 0 && tid == 0) {
        double sb = 0.0;
        #pragma unroll
        for (int k = 0; k < KCLS; k++) sb += (double)s_cntf[k] * (double)s_inter[k];
        g_Sb = sb;
    }

    // --- main loop: warp-per-4-rows, 8 loads in flight, 4 overlapped reduces ---
    const float4* cm4 = (const float4*)s_cm;
    const int gw = blockIdx.x * 8 + w;
    const int nw = gridDim.x * 8;
    double sw = 0.0;
    for (int r0 = gw * 4; r0 < ROWS; r0 += nw * 4) {
        const int4 L = *(const int4*)(lab + r0);
        const size_t base = (size_t)r0 * D4;
        const float4 a0 = xT[base       + lane], b0 = xT[base +  32 + lane];
        const float4 a1 = xT[base +  64 + lane], b1 = xT[base +  96 + lane];
        const float4 a2 = xT[base + 128 + lane], b2 = xT[base + 160 + lane];
        const float4 a3 = xT[base + 192 + lane], b3 = xT[base + 224 + lane];
        const float4* m0 = &cm4[L.x * D4];
        const float4* m1 = &cm4[L.y * D4];
        const float4* m2 = &cm4[L.z * D4];
        const float4* m3 = &cm4[L.w * D4];
        float v0 = dist8(a0, b0, m0[lane], m0[lane + 32]);
        float v1 = dist8(a1, b1, m1[lane], m1[lane + 32]);
        float v2 = dist8(a2, b2, m2[lane], m2[lane + 32]);
        float v3 = dist8(a3, b3, m3[lane], m3[lane + 32]);
        #pragma unroll
        for (int off = 16; off; off >>= 1) {
            v0 += __shfl_down_sync(0xffffffffu, v0, off);
            v1 += __shfl_down_sync(0xffffffffu, v1, off);
            v2 += __shfl_down_sync(0xffffffffu, v2, off);
            v3 += __shfl_down_sync(0xffffffffu, v3, off);
        }
        if (lane == 0) {
            const float s0 = s_inter[L.x] / (v0 + EPSF);
            const float s1 = s_inter[L.y] / (v1 + EPSF);
            const float s2 = s_inter[L.z] / (v2 + EPSF);
            const float s3 = s_inter[L.w] / (v3 + EPSF);
            *(float4*)&g_fs[r0] = make_float4(s0, s1, s2, s3);
            sw += (double)v0; sw += (double)v1;
            sw += (double)v2; sw += (double)v3;
        }
    }
    if (lane == 0) atomicAdd(&g_Sw, sw);
}

// ---------------- kernel 3: fused top-64 + gather + loss ----------------
// One block per n. Exact jax.lax.top_k semantics: rank by (value desc, index
// asc), select rank<TOPK, emit in ascending index order. Then gather.
// Output element2 index for (c,j,v) is exactly n*4800 + e.
__global__ void k_topkgather(const float2* __restrict__ x,
                             float* __restrict__ out, int sel_off) {
    __shared__ float s_v[TB];
    __shared__ unsigned char s_flag[TB];
    __shared__ int s_idx[TOPK];
    const int n = blockIdx.x;
    const int t = threadIdx.x;
    if (t < TB) {
        const float a = g_fs[(n*2 + 0)*TB + t];
        const float b = g_fs[(n*2 + 1)*TB + t];
        s_v[t] = 0.5f * (a + b);
    }
    if (n == 0 && t == 0 && sel_off >= 1)
        out[0] = (float)(g_Sw / (g_Sb + 1e-8));
    __syncthreads();
    if (t < TB) {
        const float v = s_v[t];
        int rank = 0;
        for (int j = 0; j < TB; j++) {
            const float vj = s_v[j];
            rank += (vj > v) || (vj == v && j < t);
        }
        s_flag[t] = (rank < TOPK) ? 1 : 0;
    }
    __syncthreads();
    if (t < TB && s_flag[t]) {
        int pos = 0;
        for (int j = 0; j < t; j++) pos += s_flag[j];
        s_idx[pos] = t;
    }
    __syncthreads();
    const int TOT = CC * TOPK * VV;   // 4800 float2 elements per n
    for (int e = t; e < TOT; e += blockDim.x) {
        const int v = e % VV;
        const int rem = e / VV;
        const int j = rem % TOPK;
        const int c = rem / TOPK;
        const int tt = s_idx[j];
        const float2 val = x[(((size_t)(n*CC + c)) * TB + tt) * VV + v];
        float* op = out + sel_off + 2 * ((size_t)n * TOT + e);
        op[0] = val.x;
        op[1] = val.y;
    }
}

extern "C" void kernel_launch(void* const* d_in, const int* in_sizes, int n_in,
                              void* d_out, int out_size) {
    const float2* x   = (const float2*)d_in[0];   // x [256,3,300,25,2]
    const float4* xT  = (const float4*)d_in[1];   // x_T [153600, 256]
    const int*    lab = (const int*)d_in[2];      // labels [153600] int32
    float* out = (float*)d_out;

    const int sel_off = out_size - SEL_ELEMS;     // loss scalar(s) precede x_select

    k_init<<<5, 256>>>();
    k_segsum<<<592, 256>>>(xT, lab);
    k_intra<<<592, 256>>>(xT, lab);
    k_topkgather<<<NB, 320>>>(x, out, sel_off);
}